// round 16
// baseline (speedup 1.0000x reference)
#include <cuda_runtime.h>

#define BB 16
#define TT 4096
#define DD 512
#define GRID 148
#define NTHR 896
#define NWARP 28
#define NCOMB 9005   // 10*30*30 digit combos + 5 non-digit tokens

// PAD=10, BOS=11, EOS=12, ROW=13, SEP=14; digits 0..9

__device__ unsigned g_rc_t[TT * BB];        // [t][b] : r | c<<8 | tok<<16
__device__ float g_srow[30 * DD];
__device__ float g_scol[30 * DD];
__device__ float g_comb[(size_t)NCOMB * DD];   // 18.44 MB, L2-resident
__device__ float2 g_SQcomb[NCOMB];          // per-combo (sum, sumsq)
__device__ float2 g_SQpos[TT];              // per-t (sum, sumsq) of pos row
__device__ unsigned g_scan_flag = 0;
__device__ unsigned g_pre_flag = 0;
__device__ unsigned g_pos_flag = 0;
__device__ unsigned g_comb_flag = 0;
__device__ unsigned g_done = 0;

// ---------------------------------------------------------------------------
// Packed transition-function monoid (2 words)
// ---------------------------------------------------------------------------
struct P { unsigned a, b; };

__device__ __forceinline__ P pidentity() { P p; p.a = 2u; p.b = 0u; return p; }

__device__ __forceinline__ P pcompose(P x, P y) {   // apply x, then y
    unsigned xg0 = x.a & 1u, xg1 = (x.a >> 1) & 1u;
    unsigned yg0 = y.a & 1u, yg1 = (y.a >> 1) & 1u;
    unsigned g0 = xg0 ? yg1 : yg0;
    unsigned g1 = xg1 ? yg1 : yg0;
    unsigned yrC = y.a & 4u;
    unsigned rV = yrC ? (y.a >> 8) : ((x.a >> 8) + (y.a >> 8));
    unsigned rC = (x.a & 4u) | yrC;
    unsigned xc0C = (x.a >> 3) & 1u, xc1C = (x.a >> 4) & 1u;
    unsigned yc0C = (y.a >> 3) & 1u, yc1C = (y.a >> 4) & 1u;
    unsigned xc0 = x.b & 0xffffu, xc1 = x.b >> 16;
    unsigned yc0 = y.b & 0xffffu, yc1 = y.b >> 16;
    unsigned bC0 = xg0 ? yc1C : yc0C;
    unsigned bV0 = xg0 ? yc1  : yc0;
    unsigned c0C = bC0 | xc0C;
    unsigned c0  = bC0 ? bV0 : xc0 + bV0;
    unsigned bC1 = xg1 ? yc1C : yc0C;
    unsigned bV1 = xg1 ? yc1  : yc0;
    unsigned c1C = bC1 | xc1C;
    unsigned c1  = bC1 ? bV1 : xc1 + bV1;
    P r;
    r.a = g0 | (g1 << 1) | rC | (c0C << 3) | (c1C << 4) | (rV << 8);
    r.b = c0 | (c1 << 16);
    return r;
}

__device__ __forceinline__ P pshfl_up(P p, int off) {
    P r;
    r.a = __shfl_up_sync(0xffffffffu, p.a, off);
    r.b = __shfl_up_sync(0xffffffffu, p.b, off);
    return r;
}

// ---------------------------------------------------------------------------
// Fused persistent kernel. grid=148, 896 thr (28 warps), ~66KB smem.
// Phases:
//   role: blocks 0..15 scan | 16..79 srow/scol | 80..147 pos S/Q
//   all:  build g_comb + g_SQcomb (warp-per-combo)
//   all:  main loop — warp-per-t, 16 rows, dual-row software pipeline
// ---------------------------------------------------------------------------
__global__ void __launch_bounds__(NTHR, 1) fused_kernel(
    const int* __restrict__ ids,
    const float* __restrict__ row_tab,   // (30, 256)
    const float* __restrict__ col_tab,   // (30, 256)
    const float* __restrict__ W,         // (512, 512) e-major
    const float* __restrict__ tok_tab,   // (15, 512)
    const float* __restrict__ pos_tab,   // (4096, 512)
    const float* __restrict__ gamma,
    const float* __restrict__ beta,
    float* __restrict__ out)
{
    extern __shared__ __align__(16) char s_raw[];
    const int tid = threadIdx.x;
    const int lane = tid & 31;
    const int warp = tid >> 5;

    // gamma/beta staging area: last 4KB of smem
    float4* gb_s = (float4*)(s_raw + 61440);   // [256] float4: gamma | beta
    if (tid < 128) gb_s[tid] = ((const float4*)gamma)[tid];
    else if (tid < 256) gb_s[tid] = ((const float4*)beta)[tid - 128];

    // ======================= ROLE PHASE =======================
    if (blockIdx.x < 16) {
        // ---------------- SCAN (512 active threads, 8 tok/thr) ----------------
        int* toks = (int*)s_raw;                   // [4096]
        P* warpTot = (P*)(s_raw + TT * 4);         // [16]
        P* warpPreInc = warpTot + 16;              // [16]

        const int b = blockIdx.x;
        const int* base = ids + b * TT;
        for (int i = tid; i < TT; i += NTHR) toks[i] = base[i];
        __syncthreads();

        P inc;
        if (tid < 512) {
            const int* my = toks + tid * 8;
            int fg0 = 0, fg1 = 1, frC = 0, frV = 0;
            int fc0C = 0, fc0 = 0, fc1C = 0, fc1 = 0;
            #pragma unroll
            for (int j = 0; j < 8; j++) {
                int tok = my[j];
                int bos = (tok == 11), sep = (tok == 14), rw = (tok == 13);
                int end = (tok == 12) | (tok == 10);
                int dig = (tok <= 9);
                if (bos | sep) { frC = 1; frV = 0; }
                else if (rw) frV++;
                {
                    int gc = fg0 & dig;
                    if (bos | sep | rw) { fc0C = 1; fc0 = 0; }
                    else if (gc) fc0++;
                    fg0 = bos ? 1 : (end ? 0 : fg0);
                }
                {
                    int gc = fg1 & dig;
                    if (bos | sep | rw) { fc1C = 1; fc1 = 0; }
                    else if (gc) fc1++;
                    fg1 = bos ? 1 : (end ? 0 : fg1);
                }
            }
            inc.a = (unsigned)fg0 | ((unsigned)fg1 << 1) | ((unsigned)frC << 2)
                  | ((unsigned)fc0C << 3) | ((unsigned)fc1C << 4) | ((unsigned)frV << 8);
            inc.b = (unsigned)fc0 | ((unsigned)fc1 << 16);

            #pragma unroll
            for (int off = 1; off < 32; off <<= 1) {
                P prev = pshfl_up(inc, off);
                if (lane >= off) inc = pcompose(prev, inc);
            }
            if (lane == 31) warpTot[warp] = inc;
        }
        __syncthreads();

        if (tid < 32) {
            P v = (tid < 16) ? warpTot[tid] : pidentity();
            #pragma unroll
            for (int off = 1; off < 16; off <<= 1) {
                P prev = pshfl_up(v, off);
                if (lane >= off) v = pcompose(prev, v);
            }
            if (tid < 16) warpPreInc[tid] = v;
        }
        __syncthreads();

        if (tid < 512) {
            P wex = pshfl_up(inc, 1);
            P base_p = (warp > 0) ? warpPreInc[warp - 1] : pidentity();
            P ex = (lane > 0) ? pcompose(base_p, wex) : base_p;
            int g = (int)(ex.a & 1u);
            int r = (int)(ex.a >> 8);
            int c = (int)(ex.b & 0xffffu);

            const int* my = toks + tid * 8;
            #pragma unroll
            for (int j = 0; j < 8; j++) {
                int tok = my[j];
                int bos = (tok == 11), sep = (tok == 14), rw = (tok == 13);
                int end = (tok == 12) | (tok == 10);
                int dig = (tok <= 9);
                int gc = g & dig;
                unsigned er = gc ? (unsigned)min(r, 29) : 0u;
                unsigned ec = gc ? (unsigned)min(c, 29) : 0u;
                g_rc_t[(tid * 8 + j) * BB + b] = er | (ec << 8) | ((unsigned)tok << 16);
                g = bos ? 1 : (end ? 0 : g);
                r = (bos | sep) ? 0 : (rw ? r + 1 : r);
                c = (bos | sep | rw) ? 0 : (gc ? c + 1 : c);
            }
        }
        __threadfence();
        __syncthreads();
        if (tid == 0) atomicAdd(&g_scan_flag, 1u);
    } else if (blockIdx.x < 80) {
        // ---------------- srow/scol PRECOMPUTE (W read once total) ----------------
        float* tabs = (float*)s_raw;   // [60*256] : row_tab then col_tab
        {
            float4* t4 = (float4*)tabs;
            const float4* r4 = (const float4*)row_tab;
            const float4* c4 = (const float4*)col_tab;
            for (int i = tid; i < 30 * 64; i += NTHR) t4[i] = r4[i];
            for (int i = tid; i < 30 * 64; i += NTHR) t4[30 * 64 + i] = c4[i];
        }
        __syncthreads();

        const int task = (blockIdx.x - 16) * 16 + warp;   // 64 blocks x 16 warps
        if (warp < 16 && task < 1024) {
            const int e = task >> 1;
            const int half = task & 1;
            const float4* wp = (const float4*)(W + (size_t)e * DD + half * 256);
            const float4 w0 = __ldg(wp + lane * 2);
            const float4 w1 = __ldg(wp + lane * 2 + 1);
            float* dst = half ? g_scol : g_srow;
            const float* tb = tabs + half * 30 * 256;

            #pragma unroll 1
            for (int r = 0; r < 30; r += 2) {
                const float4* ta = (const float4*)(tb + r * 256);
                const float4* tc = (const float4*)(tb + (r + 1) * 256);
                float4 a0 = ta[lane * 2], a1 = ta[lane * 2 + 1];
                float4 b0 = tc[lane * 2], b1 = tc[lane * 2 + 1];
                float sA = a0.x * w0.x;
                sA = fmaf(a0.y, w0.y, sA); sA = fmaf(a0.z, w0.z, sA); sA = fmaf(a0.w, w0.w, sA);
                sA = fmaf(a1.x, w1.x, sA); sA = fmaf(a1.y, w1.y, sA);
                sA = fmaf(a1.z, w1.z, sA); sA = fmaf(a1.w, w1.w, sA);
                float sB = b0.x * w0.x;
                sB = fmaf(b0.y, w0.y, sB); sB = fmaf(b0.z, w0.z, sB); sB = fmaf(b0.w, w0.w, sB);
                sB = fmaf(b1.x, w1.x, sB); sB = fmaf(b1.y, w1.y, sB);
                sB = fmaf(b1.z, w1.z, sB); sB = fmaf(b1.w, w1.w, sB);
                #pragma unroll
                for (int o = 16; o > 0; o >>= 1) {
                    sA += __shfl_xor_sync(0xffffffffu, sA, o);
                    sB += __shfl_xor_sync(0xffffffffu, sB, o);
                }
                if (lane == 0) {
                    dst[r * DD + e] = sA;
                    dst[(r + 1) * DD + e] = sB;
                }
            }
        }
        __threadfence();
        __syncthreads();
        if (tid == 0) atomicAdd(&g_pre_flag, 1u);
    } else {
        // ---------------- pos S/Q (blocks 80..147) ----------------
        for (int t = (blockIdx.x - 80) * NWARP + warp; t < TT; t += 68 * NWARP) {
            const float4* pp = (const float4*)(pos_tab + (size_t)t * DD);
            float s = 0.f, q = 0.f;
            #pragma unroll
            for (int i = 0; i < 4; i++) {
                float4 p = __ldg(pp + lane + i * 32);
                s += (p.x + p.y) + (p.z + p.w);
                q = fmaf(p.x, p.x, q);
                q = fmaf(p.y, p.y, q);
                q = fmaf(p.z, p.z, q);
                q = fmaf(p.w, p.w, q);
            }
            #pragma unroll
            for (int o = 16; o > 0; o >>= 1) {
                s += __shfl_xor_sync(0xffffffffu, s, o);
                q += __shfl_xor_sync(0xffffffffu, q, o);
            }
            if (lane == 0) g_SQpos[t] = make_float2(s, q);
        }
        __threadfence();
        __syncthreads();
        if (tid == 0) atomicAdd(&g_pos_flag, 1u);
    }

    // ======================= BUILD COMBINED TABLE + S/Q =====================
    if (tid == 0) {
        while (*(volatile unsigned*)&g_pre_flag < 64u) __nanosleep(64);
    }
    __syncthreads();
    {
        for (int combo = blockIdx.x * NWARP + warp; combo < NCOMB; combo += GRID * NWARP) {
            float4* dst = (float4*)(g_comb + (size_t)combo * DD);
            float4 v[4];
            if (combo < 9000) {
                const int tok = combo / 900;
                const int rem = combo - tok * 900;
                const int r = rem / 30;
                const int c = rem - r * 30;
                #pragma unroll
                for (int i = 0; i < 4; i++) {
                    const int idx = lane + i * 32;
                    float4 t4 = __ldg((const float4*)(tok_tab + tok * DD) + idx);
                    float4 rr = __ldcg((const float4*)(g_srow + r * DD) + idx);
                    float4 cc = __ldcg((const float4*)(g_scol + c * DD) + idx);
                    v[i].x = t4.x + rr.x + cc.x;
                    v[i].y = t4.y + rr.y + cc.y;
                    v[i].z = t4.z + rr.z + cc.z;
                    v[i].w = t4.w + rr.w + cc.w;
                }
            } else {
                const int tok = combo - 9000 + 10;
                #pragma unroll
                for (int i = 0; i < 4; i++)
                    v[i] = __ldg((const float4*)(tok_tab + tok * DD) + lane + i * 32);
            }
            float s = 0.f, q = 0.f;
            #pragma unroll
            for (int i = 0; i < 4; i++) {
                dst[lane + i * 32] = v[i];
                s += (v[i].x + v[i].y) + (v[i].z + v[i].w);
                q = fmaf(v[i].x, v[i].x, q);
                q = fmaf(v[i].y, v[i].y, q);
                q = fmaf(v[i].z, v[i].z, q);
                q = fmaf(v[i].w, v[i].w, q);
            }
            #pragma unroll
            for (int o = 16; o > 0; o >>= 1) {
                s += __shfl_xor_sync(0xffffffffu, s, o);
                q += __shfl_xor_sync(0xffffffffu, q, o);
            }
            if (lane == 0) g_SQcomb[combo] = make_float2(s, q);
        }
    }
    __threadfence();
    __syncthreads();
    if (tid == 0) {
        atomicAdd(&g_comb_flag, 1u);
        while (*(volatile unsigned*)&g_comb_flag < (unsigned)GRID) __nanosleep(64);
        while (*(volatile unsigned*)&g_scan_flag < 16u) __nanosleep(64);
        while (*(volatile unsigned*)&g_pos_flag < 68u) __nanosleep(64);
    }
    __syncthreads();

    // ======================= MAIN LOOP (warp-per-t, dual-row pipeline) ======
    const float4* gam_s = gb_s;
    const float4* bet_s = gb_s + 128;
    const int t = warp * GRID + blockIdx.x;   // 4144 warps cover 4096 t's

    if (t < TT) {
        unsigned prl = 0;
        if (lane < 16) prl = __ldcg(g_rc_t + t * BB + lane);
        const float2 sqp = __ldg(g_SQpos + t);
        const float4* pp = (const float4*)(pos_tab + (size_t)t * DD);
        float4 pos0 = __ldg(pp + lane);
        float4 pos1 = __ldg(pp + lane + 32);
        float4 pos2 = __ldg(pp + lane + 64);
        float4 pos3 = __ldg(pp + lane + 96);
        const float4 pos[4] = { pos0, pos1, pos2, pos3 };

        #pragma unroll 1
        for (int j = 0; j < BB; j += 2) {
            const unsigned w0 = __shfl_sync(0xffffffffu, prl, j);
            const unsigned w1 = __shfl_sync(0xffffffffu, prl, j + 1);
            const int tk0 = w0 >> 16;
            const int tk1 = w1 >> 16;
            const int ci0 = (tk0 <= 9)
                ? (tk0 * 900 + (int)(w0 & 0xff) * 30 + (int)((w0 >> 8) & 0xff))
                : (9000 + tk0 - 10);
            const int ci1 = (tk1 <= 9)
                ? (tk1 * 900 + (int)(w1 & 0xff) * 30 + (int)((w1 >> 8) & 0xff))
                : (9000 + tk1 - 10);
            const float2 sqc0 = __ldg(g_SQcomb + ci0);
            const float2 sqc1 = __ldg(g_SQcomb + ci1);
            const float4* cb0 = (const float4*)(g_comb + (size_t)ci0 * DD);
            const float4* cb1 = (const float4*)(g_comb + (size_t)ci1 * DD);

            // both gathers issued together (MLP = 32 LDG.128)
            float4 a0[4], a1[4];
            #pragma unroll
            for (int i = 0; i < 4; i++) a0[i] = __ldg(cb0 + lane + i * 32);
            #pragma unroll
            for (int i = 0; i < 4; i++) a1[i] = __ldg(cb1 + lane + i * 32);

            float d0 = 0.f, d1 = 0.f;
            #pragma unroll
            for (int i = 0; i < 4; i++) {
                d0 = fmaf(a0[i].x, pos[i].x, d0);
                d0 = fmaf(a0[i].y, pos[i].y, d0);
                d0 = fmaf(a0[i].z, pos[i].z, d0);
                d0 = fmaf(a0[i].w, pos[i].w, d0);
                d1 = fmaf(a1[i].x, pos[i].x, d1);
                d1 = fmaf(a1[i].y, pos[i].y, d1);
                d1 = fmaf(a1[i].z, pos[i].z, d1);
                d1 = fmaf(a1[i].w, pos[i].w, d1);
            }

            // interleaved dual-chain reduction (2x ILP on the serial part)
            #pragma unroll
            for (int o = 16; o > 0; o >>= 1) {
                d0 += __shfl_xor_sync(0xffffffffu, d0, o);
                d1 += __shfl_xor_sync(0xffffffffu, d1, o);
            }

            const float sum0 = sqc0.x + sqp.x;
            const float sq0  = fmaf(2.f, d0, sqc0.y + sqp.y);
            const float mu0 = sum0 * (1.f / (float)DD);
            const float inv0 = rsqrtf(sq0 * (1.f / (float)DD) - mu0 * mu0 + 1e-5f);
            const float nb0 = -mu0 * inv0;

            const float sum1 = sqc1.x + sqp.x;
            const float sq1  = fmaf(2.f, d1, sqc1.y + sqp.y);
            const float mu1 = sum1 * (1.f / (float)DD);
            const float inv1 = rsqrtf(sq1 * (1.f / (float)DD) - mu1 * mu1 + 1e-5f);
            const float nb1 = -mu1 * inv1;

            float4* op0 = (float4*)(out + (size_t)(j * TT + t) * DD);
            float4* op1 = (float4*)(out + (size_t)((j + 1) * TT + t) * DD);
            #pragma unroll
            for (int i = 0; i < 4; i++) {
                const int idx = lane + i * 32;
                const float4 gmv = gam_s[idx];
                const float4 btv = bet_s[idx];
                float4 v;
                v.x = fmaf(fmaf(a0[i].x + pos[i].x, inv0, nb0), gmv.x, btv.x);
                v.y = fmaf(fmaf(a0[i].y + pos[i].y, inv0, nb0), gmv.y, btv.y);
                v.z = fmaf(fmaf(a0[i].z + pos[i].z, inv0, nb0), gmv.z, btv.z);
                v.w = fmaf(fmaf(a0[i].w + pos[i].w, inv0, nb0), gmv.w, btv.w);
                __stcs(op0 + idx, v);
                float4 u;
                u.x = fmaf(fmaf(a1[i].x + pos[i].x, inv1, nb1), gmv.x, btv.x);
                u.y = fmaf(fmaf(a1[i].y + pos[i].y, inv1, nb1), gmv.y, btv.y);
                u.z = fmaf(fmaf(a1[i].z + pos[i].z, inv1, nb1), gmv.z, btv.z);
                u.w = fmaf(fmaf(a1[i].w + pos[i].w, inv1, nb1), gmv.w, btv.w);
                __stcs(op1 + idx, u);
            }
        }
    }

    // ======================= FLAG RESET (replay-safe) =======================
    __syncthreads();
    if (tid == 0) {
        __threadfence();
        if (atomicAdd(&g_done, 1u) == GRID - 1) {
            g_scan_flag = 0;
            g_pre_flag = 0;
            g_pos_flag = 0;
            g_comb_flag = 0;
            __threadfence();
            g_done = 0;
        }
    }
}

// ---------------------------------------------------------------------------
extern "C" void kernel_launch(void* const* d_in, const int* in_sizes, int n_in,
                              void* d_out, int out_size) {
    const int*   ids   = (const int*)  d_in[0];
    const float* tokt  = (const float*)d_in[1];
    const float* post  = (const float*)d_in[2];
    const float* rowt  = (const float*)d_in[3];
    const float* colt  = (const float*)d_in[4];
    const float* W     = (const float*)d_in[5];
    const float* gamma = (const float*)d_in[6];
    const float* beta  = (const float*)d_in[7];
    float* out = (float*)d_out;
    (void)in_sizes; (void)n_in; (void)out_size;

    const int smem_bytes = 61440 + 4096;   // prep region + gamma/beta = 65,536 B
    cudaFuncSetAttribute(fused_kernel,
                         cudaFuncAttributeMaxDynamicSharedMemorySize, smem_bytes);

    fused_kernel<<<GRID, NTHR, smem_bytes>>>(ids, rowt, colt, W,
                                             tokt, post, gamma, beta, out);
}